// round 1
// baseline (speedup 1.0000x reference)
#include <cuda_runtime.h>
#include <math.h>

#define NG 1708
#define NH 5
#define NB 16
#define NC 34
#define TPB 256
#define NCHUNK ((NG + TPB - 1) / TPB)   // 7

// Scratch (no allocations allowed): hidden state + per-head attention partials
__device__ float g_h[NB * NG];
__device__ float g_part[NH * NB * NG];

__global__ void init_h_kernel(const float* __restrict__ x) {
    int i = blockIdx.x * blockDim.x + threadIdx.x;
    if (i < NB * NG) g_h[i] = x[i];
}

// grid: (NCHUNK, NH, NB), block: TPB threads. One block handles one (b,h) and a
// chunk of i. k/v for the whole row live in shared; inner j-loop is EX2-bound.
__global__ __launch_bounds__(TPB) void attn_kernel(
    const float* __restrict__ WQ, const float* __restrict__ WK,
    const float* __restrict__ WV)
{
    __shared__ float2 skv[NG];          // (k_j, v_j)
    __shared__ float sred[64];
    const int b = blockIdx.z, h = blockIdx.y;
    const float* __restrict__ hr = g_h + b * NG;
    const float* __restrict__ wq = WQ + h * NG;
    const float* __restrict__ wk = WK + h * NG;
    const float* __restrict__ wv = WV + h * NG;
    const int tid = threadIdx.x;

    // Cooperative load + scale into smem, track k range for stable softmax
    float kmax = -3.402823466e38f, kmin = 3.402823466e38f;
    for (int j = tid; j < NG; j += TPB) {
        float hv = hr[j];
        float k = hv * wk[j];
        float v = hv * wv[j];
        skv[j] = make_float2(k, v);
        kmax = fmaxf(kmax, k);
        kmin = fminf(kmin, k);
    }
    #pragma unroll
    for (int o = 16; o; o >>= 1) {
        kmax = fmaxf(kmax, __shfl_xor_sync(0xffffffffu, kmax, o));
        kmin = fminf(kmin, __shfl_xor_sync(0xffffffffu, kmin, o));
    }
    if ((tid & 31) == 0) { sred[tid >> 5] = kmax; sred[32 + (tid >> 5)] = kmin; }
    __syncthreads();
    if (tid == 0) {
        float M = sred[0], m = sred[32];
        #pragma unroll
        for (int w = 1; w < TPB / 32; w++) {
            M = fmaxf(M, sred[w]); m = fminf(m, sred[32 + w]);
        }
        sred[0] = M; sred[32] = m;
    }
    __syncthreads();
    kmax = sred[0]; kmin = sred[32];

    const int i = blockIdx.x * TPB + tid;
    if (i >= NG) return;

    const float LOG2E = 1.44269504088896340736f;
    float q2 = hr[i] * wq[i] * LOG2E;                    // base-2 exponent scale
    float m2 = (q2 >= 0.f) ? q2 * kmax : q2 * kmin;      // exact row max of q2*k_j
    float nm2 = -m2;

    // 4 independent accumulator chains hide EX2 (16cyc) / FADD (4cyc) latency
    float s0a = 0.f, s0b = 0.f, s0c = 0.f, s0d = 0.f;
    float s1a = 0.f, s1b = 0.f, s1c = 0.f, s1d = 0.f;
    const float4* __restrict__ p = reinterpret_cast<const float4*>(skv);
    #pragma unroll 1
    for (int t = 0; t < NG / 4; t++) {   // 427 iterations x 4 (k,v) pairs
        float4 A = p[2 * t];
        float4 Bv = p[2 * t + 1];
        float e0, e1, e2, e3;
        asm("ex2.approx.f32 %0, %1;" : "=f"(e0) : "f"(fmaf(q2, A.x,  nm2)));
        asm("ex2.approx.f32 %0, %1;" : "=f"(e1) : "f"(fmaf(q2, A.z,  nm2)));
        asm("ex2.approx.f32 %0, %1;" : "=f"(e2) : "f"(fmaf(q2, Bv.x, nm2)));
        asm("ex2.approx.f32 %0, %1;" : "=f"(e3) : "f"(fmaf(q2, Bv.z, nm2)));
        s0a += e0; s1a = fmaf(e0, A.y,  s1a);
        s0b += e1; s1b = fmaf(e1, A.w,  s1b);
        s0c += e2; s1c = fmaf(e2, Bv.y, s1c);
        s0d += e3; s1d = fmaf(e3, Bv.w, s1d);
    }
    float S0 = (s0a + s0b) + (s0c + s0d);
    float S1 = (s1a + s1b) + (s1c + s1d);

    // diagonal zeroed AFTER softmax: subtract its numerator term only
    float2 kvi = skv[i];
    float ed;
    asm("ex2.approx.f32 %0, %1;" : "=f"(ed) : "f"(fmaf(q2, kvi.x, nm2)));
    g_part[(h * NB + b) * NG + i] = (S1 - ed * kvi.y) / S0;
}

// grid: NB blocks. Sums heads, layernorm (ddof=1, /(std+eps)), residual add.
__global__ __launch_bounds__(256) void ln_kernel(
    const float* __restrict__ W0, const float* __restrict__ ln_a,
    const float* __restrict__ ln_b)
{
    __shared__ float sa[NG];
    __shared__ float sred[32];
    __shared__ float s_bcast;
    const int b = blockIdx.x, tid = threadIdx.x;

    float w0[NH];
    #pragma unroll
    for (int h = 0; h < NH; h++) w0[h] = W0[h];

    float sum = 0.f;
    for (int i = tid; i < NG; i += 256) {
        float a = 0.f;
        #pragma unroll
        for (int h = 0; h < NH; h++)
            a = fmaf(w0[h], g_part[(h * NB + b) * NG + i], a);
        sa[i] = a;
        sum += a;
    }
    // block-sum -> mean
    #pragma unroll
    for (int o = 16; o; o >>= 1) sum += __shfl_xor_sync(0xffffffffu, sum, o);
    if ((tid & 31) == 0) sred[tid >> 5] = sum;
    __syncthreads();
    if (tid == 0) {
        float t = 0.f;
        #pragma unroll
        for (int w = 0; w < 8; w++) t += sred[w];
        s_bcast = t / (float)NG;
    }
    __syncthreads();
    float mean = s_bcast;

    float vs = 0.f;
    for (int i = tid; i < NG; i += 256) {
        float d = sa[i] - mean;
        vs = fmaf(d, d, vs);
    }
    #pragma unroll
    for (int o = 16; o; o >>= 1) vs += __shfl_xor_sync(0xffffffffu, vs, o);
    if ((tid & 31) == 0) sred[tid >> 5] = vs;
    __syncthreads();
    if (tid == 0) {
        float t = 0.f;
        #pragma unroll
        for (int w = 0; w < 8; w++) t += sred[w];
        float stdv = sqrtf(t / (float)(NG - 1));
        s_bcast = 1.f / (stdv + 1e-6f);
    }
    __syncthreads();
    float inv = s_bcast;

    for (int i = tid; i < NG; i += 256)
        g_h[b * NG + i] += ln_a[i] * (sa[i] - mean) * inv + ln_b[i];
}

// grid: NB blocks, 128 threads. logits + log_softmax
__global__ __launch_bounds__(128) void fc_kernel(
    const float* __restrict__ fc_w, const float* __restrict__ fc_b,
    float* __restrict__ out)
{
    __shared__ float slog[NC];
    __shared__ float s_ls;
    const int b = blockIdx.x, tid = threadIdx.x;
    const int w = tid >> 5, l = tid & 31;
    const float* __restrict__ hr = g_h + b * NG;

    for (int c = w; c < NC; c += 4) {
        const float* __restrict__ wr = fc_w + c * NG;
        float d = 0.f;
        for (int j = l; j < NG; j += 32) d = fmaf(hr[j], wr[j], d);
        #pragma unroll
        for (int o = 16; o; o >>= 1) d += __shfl_xor_sync(0xffffffffu, d, o);
        if (l == 0) slog[c] = d + fc_b[c];
    }
    __syncthreads();
    if (tid == 0) {
        float M = slog[0];
        for (int c = 1; c < NC; c++) M = fmaxf(M, slog[c]);
        float s = 0.f;
        for (int c = 0; c < NC; c++) s += expf(slog[c] - M);
        s_ls = M + logf(s);
    }
    __syncthreads();
    if (tid < NC) out[b * NC + tid] = slog[tid] - s_ls;
}

extern "C" void kernel_launch(void* const* d_in, const int* in_sizes, int n_in,
                              void* d_out, int out_size) {
    const float* x    = (const float*)d_in[0];
    const float* WQ[3] = {(const float*)d_in[1], (const float*)d_in[5], (const float*)d_in[9]};
    const float* WK[3] = {(const float*)d_in[2], (const float*)d_in[6], (const float*)d_in[10]};
    const float* WV[3] = {(const float*)d_in[3], (const float*)d_in[7], (const float*)d_in[11]};
    const float* W0[3] = {(const float*)d_in[4], (const float*)d_in[8], (const float*)d_in[12]};
    const float* ln_a = (const float*)d_in[13];
    const float* ln_b = (const float*)d_in[14];
    const float* fc_w = (const float*)d_in[15];
    const float* fc_b = (const float*)d_in[16];

    init_h_kernel<<<(NB * NG + 255) / 256, 256>>>(x);
    for (int L = 0; L < 3; L++) {
        attn_kernel<<<dim3(NCHUNK, NH, NB), TPB>>>(WQ[L], WK[L], WV[L]);
        ln_kernel<<<NB, 256>>>(W0[L], ln_a, ln_b);
    }
    fc_kernel<<<NB, 128>>>(fc_w, fc_b, (float*)d_out);
}

// round 2
// speedup vs baseline: 1.1198x; 1.1198x over previous
#include <cuda_runtime.h>
#include <math.h>

#define NG 1708
#define NGP 1712          // padded to multiple of 8
#define NH 5
#define NB 16
#define NC 34
#define TPB 256
#define NCHUNK ((NG + TPB - 1) / TPB)   // 7

// Scratch (no allocations allowed): hidden state + per-head attention partials
__device__ float g_h[NB * NG];
__device__ float g_part[NH * NB * NG];

__device__ __forceinline__ void fma2(unsigned long long& d, unsigned long long a,
                                     unsigned long long b, unsigned long long c) {
    asm("fma.rn.f32x2 %0, %1, %2, %3;" : "=l"(d) : "l"(a), "l"(b), "l"(c));
}
__device__ __forceinline__ void unpack2(float& lo, float& hi, unsigned long long p) {
    asm("mov.b64 {%0, %1}, %2;" : "=f"(lo), "=f"(hi) : "l"(p));
}
__device__ __forceinline__ float ex2(float a) {
    float r; asm("ex2.approx.f32 %0, %1;" : "=f"(r) : "f"(a)); return r;
}

// grid: (NCHUNK, NH, NB), block TPB. One block = one (b,h), chunk of i rows.
__global__ __launch_bounds__(TPB) void attn_kernel(
    const float* __restrict__ x, int use_x,
    const float* __restrict__ WQ, const float* __restrict__ WK,
    const float* __restrict__ WV)
{
    __shared__ float sk[NGP];
    __shared__ float sv[NGP];
    __shared__ float sred[64];
    const int b = blockIdx.z, h = blockIdx.y;
    const float* __restrict__ hr = (use_x ? x : g_h) + b * NG;
    const float* __restrict__ wq = WQ + h * NG;
    const float* __restrict__ wk = WK + h * NG;
    const float* __restrict__ wv = WV + h * NG;
    const int tid = threadIdx.x;

    // Cooperative load + scale into smem (k, v separate); pad tail with zeros.
    float kmax = -3.402823466e38f, kmin = 3.402823466e38f;
    for (int j = tid; j < NGP; j += TPB) {
        float k = 0.f, v = 0.f;
        if (j < NG) {
            float hv = hr[j];
            k = hv * wk[j];
            v = hv * wv[j];
        }
        sk[j] = k; sv[j] = v;
        kmax = fmaxf(kmax, k);
        kmin = fminf(kmin, k);
    }
    #pragma unroll
    for (int o = 16; o; o >>= 1) {
        kmax = fmaxf(kmax, __shfl_xor_sync(0xffffffffu, kmax, o));
        kmin = fminf(kmin, __shfl_xor_sync(0xffffffffu, kmin, o));
    }
    if ((tid & 31) == 0) { sred[tid >> 5] = kmax; sred[32 + (tid >> 5)] = kmin; }
    __syncthreads();
    if (tid == 0) {
        float M = sred[0], m = sred[32];
        #pragma unroll
        for (int w = 1; w < TPB / 32; w++) {
            M = fmaxf(M, sred[w]); m = fminf(m, sred[32 + w]);
        }
        sred[0] = M; sred[32] = m;
    }
    __syncthreads();
    kmax = sred[0]; kmin = sred[32];

    const int i = blockIdx.x * TPB + tid;
    if (i >= NG) return;

    const float LOG2E = 1.44269504088896340736f;
    float q2 = hr[i] * wq[i] * LOG2E;                 // base-2 exponent scale
    float m2 = (q2 >= 0.f) ? q2 * kmax : q2 * kmin;   // upper bound of q2*k_j
    float nm2 = -m2;

    unsigned long long qq, mm;
    asm("mov.b64 %0, {%1, %2};" : "=l"(qq) : "f"(q2),  "f"(q2));
    asm("mov.b64 %0, {%1, %2};" : "=l"(mm) : "f"(nm2), "f"(nm2));

    float s0a = 0.f, s0b = 0.f, s0c = 0.f, s0d = 0.f;
    float s1a = 0.f, s1b = 0.f, s1c = 0.f, s1d = 0.f;
    const ulonglong2* __restrict__ kp = reinterpret_cast<const ulonglong2*>(sk);
    const float4*     __restrict__ vp = reinterpret_cast<const float4*>(sv);
    #pragma unroll 1
    for (int t = 0; t < NGP / 8; t++) {     // 214 iterations, 8 j's each
        ulonglong2 ka = kp[2 * t];          // k0..k3 as two packed f32x2
        ulonglong2 kb = kp[2 * t + 1];      // k4..k7
        float4 va = vp[2 * t];
        float4 vb = vp[2 * t + 1];
        unsigned long long a01, a23, a45, a67;
        fma2(a01, qq, ka.x, mm);
        fma2(a23, qq, ka.y, mm);
        fma2(a45, qq, kb.x, mm);
        fma2(a67, qq, kb.y, mm);
        float x0, x1, x2, x3, x4, x5, x6, x7;
        unpack2(x0, x1, a01); unpack2(x2, x3, a23);
        unpack2(x4, x5, a45); unpack2(x6, x7, a67);
        float e0 = ex2(x0), e1 = ex2(x1), e2 = ex2(x2), e3 = ex2(x3);
        float e4 = ex2(x4), e5 = ex2(x5), e6 = ex2(x6), e7 = ex2(x7);
        s0a += e0; s1a = fmaf(e0, va.x, s1a);
        s0b += e1; s1b = fmaf(e1, va.y, s1b);
        s0c += e2; s1c = fmaf(e2, va.z, s1c);
        s0d += e3; s1d = fmaf(e3, va.w, s1d);
        s0a += e4; s1a = fmaf(e4, vb.x, s1a);
        s0b += e5; s1b = fmaf(e5, vb.y, s1b);
        s0c += e6; s1c = fmaf(e6, vb.z, s1c);
        s0d += e7; s1d = fmaf(e7, vb.w, s1d);
    }
    float S0 = (s0a + s0b) + (s0c + s0d);
    float S1 = (s1a + s1b) + (s1c + s1d);

    // remove the 4 zero-padded j's: each contributed exp2(q2*0 - m2)
    S0 -= 4.f * ex2(nm2);
    // diagonal zeroed AFTER softmax: subtract its numerator term only
    float ed = ex2(fmaf(q2, sk[i], nm2));
    g_part[(h * NB + b) * NG + i] = (S1 - ed * sv[i]) / S0;
}

// grid: NB blocks, 512 threads. Head-sum, layernorm (ddof=1), residual add.
__global__ __launch_bounds__(512) void ln_kernel(
    const float* __restrict__ x, int use_x,
    const float* __restrict__ W0, const float* __restrict__ ln_a,
    const float* __restrict__ ln_b)
{
    __shared__ float sa[NG];
    __shared__ float sred[16];
    __shared__ float s_bcast;
    const int b = blockIdx.x, tid = threadIdx.x;
    const float* __restrict__ base = (use_x ? x : g_h) + b * NG;

    float w0[NH];
    #pragma unroll
    for (int h = 0; h < NH; h++) w0[h] = W0[h];

    float sum = 0.f;
    for (int i = tid; i < NG; i += 512) {
        float a = 0.f;
        #pragma unroll
        for (int h = 0; h < NH; h++)
            a = fmaf(w0[h], g_part[(h * NB + b) * NG + i], a);
        sa[i] = a;
        sum += a;
    }
    #pragma unroll
    for (int o = 16; o; o >>= 1) sum += __shfl_xor_sync(0xffffffffu, sum, o);
    if ((tid & 31) == 0) sred[tid >> 5] = sum;
    __syncthreads();
    if (tid == 0) {
        float t = 0.f;
        #pragma unroll
        for (int w = 0; w < 16; w++) t += sred[w];
        s_bcast = t / (float)NG;
    }
    __syncthreads();
    float mean = s_bcast;

    float vs = 0.f;
    for (int i = tid; i < NG; i += 512) {
        float d = sa[i] - mean;
        vs = fmaf(d, d, vs);
    }
    #pragma unroll
    for (int o = 16; o; o >>= 1) vs += __shfl_xor_sync(0xffffffffu, vs, o);
    if ((tid & 31) == 0) sred[tid >> 5] = vs;
    __syncthreads();
    if (tid == 0) {
        float t = 0.f;
        #pragma unroll
        for (int w = 0; w < 16; w++) t += sred[w];
        float stdv = sqrtf(t / (float)(NG - 1));
        s_bcast = 1.f / (stdv + 1e-6f);
    }
    __syncthreads();
    float inv = s_bcast;

    for (int i = tid; i < NG; i += 512)
        g_h[b * NG + i] = base[i] + ln_a[i] * (sa[i] - mean) * inv + ln_b[i];
}

// grid: NB blocks, 1024 threads (32 warps). One warp per class; log_softmax.
__global__ __launch_bounds__(1024) void fc_kernel(
    const float* __restrict__ fc_w, const float* __restrict__ fc_b,
    float* __restrict__ out)
{
    __shared__ float slog[NC];
    __shared__ float s_ls;
    const int b = blockIdx.x, tid = threadIdx.x;
    const int w = tid >> 5, l = tid & 31;
    const float4* __restrict__ hv = reinterpret_cast<const float4*>(g_h + b * NG);

    for (int c = w; c < NC; c += 32) {
        const float4* __restrict__ wr = reinterpret_cast<const float4*>(fc_w + c * NG);
        float d = 0.f;
        for (int j = l; j < NG / 4; j += 32) {      // 427 float4's
            float4 a = hv[j], q = wr[j];
            d = fmaf(a.x, q.x, d); d = fmaf(a.y, q.y, d);
            d = fmaf(a.z, q.z, d); d = fmaf(a.w, q.w, d);
        }
        #pragma unroll
        for (int o = 16; o; o >>= 1) d += __shfl_xor_sync(0xffffffffu, d, o);
        if (l == 0) slog[c] = d + fc_b[c];
    }
    __syncthreads();
    if (tid == 0) {
        float M = slog[0];
        #pragma unroll
        for (int c = 1; c < NC; c++) M = fmaxf(M, slog[c]);
        float s = 0.f;
        for (int c = 0; c < NC; c++) s += expf(slog[c] - M);
        s_ls = M + logf(s);
    }
    __syncthreads();
    if (tid < NC) out[b * NC + tid] = slog[tid] - s_ls;
}

extern "C" void kernel_launch(void* const* d_in, const int* in_sizes, int n_in,
                              void* d_out, int out_size) {
    const float* x    = (const float*)d_in[0];
    const float* WQ[3] = {(const float*)d_in[1], (const float*)d_in[5], (const float*)d_in[9]};
    const float* WK[3] = {(const float*)d_in[2], (const float*)d_in[6], (const float*)d_in[10]};
    const float* WV[3] = {(const float*)d_in[3], (const float*)d_in[7], (const float*)d_in[11]};
    const float* W0[3] = {(const float*)d_in[4], (const float*)d_in[8], (const float*)d_in[12]};
    const float* ln_a = (const float*)d_in[13];
    const float* ln_b = (const float*)d_in[14];
    const float* fc_w = (const float*)d_in[15];
    const float* fc_b = (const float*)d_in[16];

    for (int L = 0; L < 3; L++) {
        attn_kernel<<<dim3(NCHUNK, NH, NB), TPB>>>(x, L == 0 ? 1 : 0,
                                                   WQ[L], WK[L], WV[L]);
        ln_kernel<<<NB, 512>>>(x, L == 0 ? 1 : 0, W0[L], ln_a, ln_b);
    }
    fc_kernel<<<NB, 1024>>>(fc_w, fc_b, (float*)d_out);
}

// round 4
// speedup vs baseline: 1.1612x; 1.0370x over previous
#include <cuda_runtime.h>
#include <math.h>

#define NG 1708
#define NGV (NG / 4)      // 427 float4s, exact
#define NGP 1712          // padded to multiple of 8
#define NH 5
#define NB 16
#define NC 34
#define TPB 256
#define NCHUNK ((NG + TPB - 1) / TPB)   // 7

// Scratch (no allocations allowed): hidden state + per-head attention partials
__device__ float g_h[NB * NG];
__device__ float g_part[NH * NB * NG];

__device__ __forceinline__ void fma2(unsigned long long& d, unsigned long long a,
                                     unsigned long long b, unsigned long long c) {
    asm("fma.rn.f32x2 %0, %1, %2, %3;" : "=l"(d) : "l"(a), "l"(b), "l"(c));
}
__device__ __forceinline__ void unpack2(float& lo, float& hi, unsigned long long p) {
    asm("mov.b64 {%0, %1}, %2;" : "=f"(lo), "=f"(hi) : "l"(p));
}
__device__ __forceinline__ float ex2(float a) {
    float r; asm("ex2.approx.f32 %0, %1;" : "=f"(r) : "f"(a)); return r;
}

// grid: (NCHUNK, NH, NB), block TPB. One block = one (b,h), chunk of i rows.
__global__ __launch_bounds__(TPB) void attn_kernel(
    const float* __restrict__ x, int use_x,
    const float* __restrict__ WQ, const float* __restrict__ WK,
    const float* __restrict__ WV)
{
    __shared__ float sk[NGP];
    __shared__ float sv[NGP];
    __shared__ float sred[64];
    const int b = blockIdx.z, h = blockIdx.y;
    const float* __restrict__ hr = (use_x ? x : g_h) + b * NG;
    const float* __restrict__ wq = WQ + h * NG;
    const float* __restrict__ wk = WK + h * NG;
    const float* __restrict__ wv = WV + h * NG;
    const int tid = threadIdx.x;

    // Cooperative load + scale into smem (k, v separate); pad tail with zeros.
    float kmax = -3.402823466e38f, kmin = 3.402823466e38f;
    for (int j = tid; j < NGP; j += TPB) {
        float k = 0.f, v = 0.f;
        if (j < NG) {
            float hv = hr[j];
            k = hv * wk[j];
            v = hv * wv[j];
        }
        sk[j] = k; sv[j] = v;
        kmax = fmaxf(kmax, k);
        kmin = fminf(kmin, k);
    }
    #pragma unroll
    for (int o = 16; o; o >>= 1) {
        kmax = fmaxf(kmax, __shfl_xor_sync(0xffffffffu, kmax, o));
        kmin = fminf(kmin, __shfl_xor_sync(0xffffffffu, kmin, o));
    }
    if ((tid & 31) == 0) { sred[tid >> 5] = kmax; sred[32 + (tid >> 5)] = kmin; }
    __syncthreads();
    if (tid == 0) {
        float M = sred[0], m = sred[32];
        #pragma unroll
        for (int w = 1; w < TPB / 32; w++) {
            M = fmaxf(M, sred[w]); m = fminf(m, sred[32 + w]);
        }
        sred[0] = M; sred[32] = m;
    }
    __syncthreads();
    kmax = sred[0]; kmin = sred[32];

    const int i = blockIdx.x * TPB + tid;
    if (i >= NG) return;

    const float LOG2E = 1.44269504088896340736f;
    float q2 = hr[i] * wq[i] * LOG2E;                 // base-2 exponent scale
    float m2 = (q2 >= 0.f) ? q2 * kmax : q2 * kmin;   // upper bound of q2*k_j
    float nm2 = -m2;

    unsigned long long qq, mm;
    asm("mov.b64 %0, {%1, %2};" : "=l"(qq) : "f"(q2),  "f"(q2));
    asm("mov.b64 %0, {%1, %2};" : "=l"(mm) : "f"(nm2), "f"(nm2));

    float s0a = 0.f, s0b = 0.f, s0c = 0.f, s0d = 0.f;
    float s1a = 0.f, s1b = 0.f, s1c = 0.f, s1d = 0.f;
    const ulonglong2* __restrict__ kp = reinterpret_cast<const ulonglong2*>(sk);
    const float4*     __restrict__ vp = reinterpret_cast<const float4*>(sv);
    #pragma unroll 1
    for (int t = 0; t < NGP / 8; t++) {     // 214 iterations, 8 j's each
        ulonglong2 ka = kp[2 * t];          // k0..k3 as two packed f32x2
        ulonglong2 kb = kp[2 * t + 1];      // k4..k7
        float4 va = vp[2 * t];
        float4 vb = vp[2 * t + 1];
        unsigned long long a01, a23, a45, a67;
        fma2(a01, qq, ka.x, mm);
        fma2(a23, qq, ka.y, mm);
        fma2(a45, qq, kb.x, mm);
        fma2(a67, qq, kb.y, mm);
        float x0, x1, x2, x3, x4, x5, x6, x7;
        unpack2(x0, x1, a01); unpack2(x2, x3, a23);
        unpack2(x4, x5, a45); unpack2(x6, x7, a67);
        float e0 = ex2(x0), e1 = ex2(x1), e2 = ex2(x2), e3 = ex2(x3);
        float e4 = ex2(x4), e5 = ex2(x5), e6 = ex2(x6), e7 = ex2(x7);
        s0a += e0; s1a = fmaf(e0, va.x, s1a);
        s0b += e1; s1b = fmaf(e1, va.y, s1b);
        s0c += e2; s1c = fmaf(e2, va.z, s1c);
        s0d += e3; s1d = fmaf(e3, va.w, s1d);
        s0a += e4; s1a = fmaf(e4, vb.x, s1a);
        s0b += e5; s1b = fmaf(e5, vb.y, s1b);
        s0c += e6; s1c = fmaf(e6, vb.z, s1c);
        s0d += e7; s1d = fmaf(e7, vb.w, s1d);
    }
    float S0 = (s0a + s0b) + (s0c + s0d);
    float S1 = (s1a + s1b) + (s1c + s1d);

    // remove the 4 zero-padded j's: each contributed exp2(q2*0 - m2)
    S0 -= 4.f * ex2(nm2);
    // diagonal zeroed AFTER softmax: subtract its numerator term only
    float ed = ex2(fmaf(q2, sk[i], nm2));
    g_part[(h * NB + b) * NG + i] = (S1 - ed * sv[i]) / S0;
}

// grid: NB blocks, 1024 threads. Single-pass head-sum + LN (ddof=1) + residual.
// On the last layer (do_fc) the same block computes FC + log_softmax for its b.
__global__ __launch_bounds__(1024) void ln_fc_kernel(
    const float* __restrict__ x, int use_x,
    const float* __restrict__ W0, const float* __restrict__ ln_a,
    const float* __restrict__ ln_b, int do_fc,
    const float* __restrict__ fc_w, const float* __restrict__ fc_b,
    float* __restrict__ out)
{
    __shared__ float4 sa4[NGV];
    __shared__ float sred[64];
    __shared__ float sb[2];
    __shared__ float slog[NC];
    __shared__ float s_ls;
    const int b = blockIdx.x, tid = threadIdx.x;
    const int w = tid >> 5, l = tid & 31;
    const float4* __restrict__ base4 =
        reinterpret_cast<const float4*>((use_x ? x : g_h) + b * NG);

    float w0[NH];
    #pragma unroll
    for (int h = 0; h < NH; h++) w0[h] = W0[h];

    float s = 0.f, ss = 0.f;
    if (tid < NGV) {
        float4 a = make_float4(0.f, 0.f, 0.f, 0.f);
        #pragma unroll
        for (int h = 0; h < NH; h++) {
            float4 p = reinterpret_cast<const float4*>(
                g_part + (h * NB + b) * NG)[tid];
            a.x = fmaf(w0[h], p.x, a.x);
            a.y = fmaf(w0[h], p.y, a.y);
            a.z = fmaf(w0[h], p.z, a.z);
            a.w = fmaf(w0[h], p.w, a.w);
        }
        sa4[tid] = a;
        s = (a.x + a.y) + (a.z + a.w);
        ss = fmaf(a.x, a.x, fmaf(a.y, a.y, fmaf(a.z, a.z, a.w * a.w)));
    }
    #pragma unroll
    for (int o = 16; o; o >>= 1) {
        s  += __shfl_xor_sync(0xffffffffu, s,  o);
        ss += __shfl_xor_sync(0xffffffffu, ss, o);
    }
    if (l == 0) { sred[w] = s; sred[32 + w] = ss; }
    __syncthreads();
    if (tid == 0) {
        float S = 0.f, SS = 0.f;
        #pragma unroll
        for (int i = 0; i < 32; i++) { S += sred[i]; SS += sred[32 + i]; }
        float mean = S / (float)NG;
        float var = (SS - (float)NG * mean * mean) / (float)(NG - 1);
        var = fmaxf(var, 0.f);
        sb[0] = mean;
        sb[1] = 1.f / (sqrtf(var) + 1e-6f);
    }
    __syncthreads();
    const float mean = sb[0], inv = sb[1];

    if (tid < NGV) {
        float4 a = sa4[tid];
        float4 bs = base4[tid];
        float4 la = reinterpret_cast<const float4*>(ln_a)[tid];
        float4 lb = reinterpret_cast<const float4*>(ln_b)[tid];
        float4 o;
        o.x = bs.x + fmaf(la.x * (a.x - mean), inv, lb.x);
        o.y = bs.y + fmaf(la.y * (a.y - mean), inv, lb.y);
        o.z = bs.z + fmaf(la.z * (a.z - mean), inv, lb.z);
        o.w = bs.w + fmaf(la.w * (a.w - mean), inv, lb.w);
        reinterpret_cast<float4*>(g_h + b * NG)[tid] = o;
        sa4[tid] = o;                       // keep h3 row for fused FC
    }

    if (!do_fc) return;
    __syncthreads();

    // FC: one warp per class (32 warps cover 34 classes in 2 rounds)
    for (int c = w; c < NC; c += 32) {
        const float4* __restrict__ wr =
            reinterpret_cast<const float4*>(fc_w + c * NG);
        float d = 0.f;
        for (int j = l; j < NGV; j += 32) {
            float4 a = sa4[j], q = wr[j];
            d = fmaf(a.x, q.x, d); d = fmaf(a.y, q.y, d);
            d = fmaf(a.z, q.z, d); d = fmaf(a.w, q.w, d);
        }
        #pragma unroll
        for (int o = 16; o; o >>= 1) d += __shfl_xor_sync(0xffffffffu, d, o);
        if (l == 0) slog[c] = d + fc_b[c];
    }
    __syncthreads();
    if (tid == 0) {
        float M = slog[0];
        #pragma unroll
        for (int c = 1; c < NC; c++) M = fmaxf(M, slog[c]);
        float sum = 0.f;
        for (int c = 0; c < NC; c++) sum += expf(slog[c] - M);
        s_ls = M + logf(sum);
    }
    __syncthreads();
    if (tid < NC) out[b * NC + tid] = slog[tid] - s_ls;
}

extern "C" void kernel_launch(void* const* d_in, const int* in_sizes, int n_in,
                              void* d_out, int out_size) {
    const float* x    = (const float*)d_in[0];
    const float* WQ[3] = {(const float*)d_in[1], (const float*)d_in[5], (const float*)d_in[9]};
    const float* WK[3] = {(const float*)d_in[2], (const float*)d_in[6], (const float*)d_in[10]};
    const float* WV[3] = {(const float*)d_in[3], (const float*)d_in[7], (const float*)d_in[11]};
    const float* W0[3] = {(const float*)d_in[4], (const float*)d_in[8], (const float*)d_in[12]};
    const float* ln_a = (const float*)d_in[13];
    const float* ln_b = (const float*)d_in[14];
    const float* fc_w = (const float*)d_in[15];
    const float* fc_b = (const float*)d_in[16];

    for (int L = 0; L < 3; L++) {
        attn_kernel<<<dim3(NCHUNK, NH, NB), TPB>>>(x, L == 0 ? 1 : 0,
                                                   WQ[L], WK[L], WV[L]);
        ln_fc_kernel<<<NB, 1024>>>(x, L == 0 ? 1 : 0, W0[L], ln_a, ln_b,
                                   L == 2 ? 1 : 0, fc_w, fc_b, (float*)d_out);
    }
}